// round 1
// baseline (speedup 1.0000x reference)
#include <cuda_runtime.h>

// CostVolume: left,right [B,C,H,W] f32 -> out [B,2C,D,H,W] f32
//   out[b, c,      d, h, w] = (w+d < W) ? left [b,c,h,w+d] : 0
//   out[b, C + c,  d, h, w] = (w-d >= 0)? right[b,c,h,w-d] : 0
//
// Fixed shapes for this problem: B=2, C=32, H=128, W=256, D=32.

namespace {
constexpr int B = 2;
constexpr int C = 32;
constexpr int H = 128;
constexpr int W = 256;
constexpr int D = 32;
}

__global__ __launch_bounds__(256, 8)
void cost_volume_kernel(const float* __restrict__ left,
                        const float* __restrict__ right,
                        float* __restrict__ out) {
    __shared__ float sl[W];
    __shared__ float sr[W];

    const int blk = blockIdx.x;          // b*C*H + c*H + h
    const int h = blk & (H - 1);         // H = 128
    const int c = (blk >> 7) & (C - 1);  // C = 32
    const int b = blk >> 12;             // / (C*H) = / 4096

    const int tid = threadIdx.x;

    // Stage the two input rows (256 floats each) in shared memory.
    const size_t in_off = ((((size_t)b * C + c) * H) + h) * W;
    sl[tid] = left[in_off + tid];
    sr[tid] = right[in_off + tid];
    __syncthreads();

    // Output bases: out index = ((((b*2C + c2)*D + d)*H + h)*W + w
    const size_t dstride = (size_t)H * W;                      // per-d stride
    const size_t out_l_base =
        ((size_t)(b * 2 * C + c) * D) * dstride + (size_t)h * W;
    const size_t out_r_base =
        ((size_t)(b * 2 * C + C + c) * D) * dstride + (size_t)h * W;

    // 256 threads: tid%64 -> float4 position along W (64 * 4 = 256),
    //              tid/64 -> d sub-lane (4 d's per iteration).
    const int w4   = (tid & 63) << 2;  // 0, 4, ..., 252
    const int dsub = tid >> 6;         // 0..3

    #pragma unroll
    for (int d0 = 0; d0 < D; d0 += 4) {
        const int d = d0 + dsub;

        // Left half: out[w] = sl[w + d], zero where w + d >= W.
        const int lb = w4 + d;
        float4 v;
        v.x = (lb + 0 < W) ? sl[lb + 0] : 0.0f;
        v.y = (lb + 1 < W) ? sl[lb + 1] : 0.0f;
        v.z = (lb + 2 < W) ? sl[lb + 2] : 0.0f;
        v.w = (lb + 3 < W) ? sl[lb + 3] : 0.0f;
        *reinterpret_cast<float4*>(out + out_l_base + (size_t)d * dstride + w4) = v;

        // Right half: out[w] = sr[w - d], zero where w < d.
        const int rb = w4 - d;
        float4 u;
        u.x = (rb + 0 >= 0) ? sr[rb + 0] : 0.0f;
        u.y = (rb + 1 >= 0) ? sr[rb + 1] : 0.0f;
        u.z = (rb + 2 >= 0) ? sr[rb + 2] : 0.0f;
        u.w = (rb + 3 >= 0) ? sr[rb + 3] : 0.0f;
        *reinterpret_cast<float4*>(out + out_r_base + (size_t)d * dstride + w4) = u;
    }
}

extern "C" void kernel_launch(void* const* d_in, const int* in_sizes, int n_in,
                              void* d_out, int out_size) {
    const float* left  = (const float*)d_in[0];
    const float* right = (const float*)d_in[1];
    // d_in[2] (max_disp) is a device scalar; D=32 is fixed for this problem
    // and is needed host-side for grid dims, so it is compiled in.
    float* out = (float*)d_out;

    (void)in_sizes; (void)n_in; (void)out_size;

    const int grid = B * C * H;  // 8192 CTAs
    cost_volume_kernel<<<grid, 256>>>(left, right, out);
}

// round 2
// speedup vs baseline: 1.5800x; 1.5800x over previous
#include <cuda_runtime.h>

// CostVolume: left,right [B,C,H,W] f32 -> out [B,2C,D,H,W] f32
//   out[b, c,      d, h, w] = (w+d < W) ? left [b,c,h,w+d] : 0
//   out[b, C + c,  d, h, w] = (w-d >= 0)? right[b,c,h,w-d] : 0
//
// Fixed shapes: B=2, C=32, H=128, W=256, D=32.
//
// Strategy: pure store-roofline kernel. One CTA (128 thr) per (b,c,h) row.
// Threads 0-63 handle the left half, 64-127 the right half. Each thread owns
// one 4-float output column (w4) and ALL 32 disparities: it loads a 36-float
// register window from a zero-padded smem row ONCE (9 x LDS.128), then emits
// 32 x STG.128 by static register selection. LDS traffic = 7% of store
// traffic (vs 100% in R1); no boundary branches (zeros live in smem pads).

namespace {
constexpr int B = 2;
constexpr int C = 32;
constexpr int H = 128;
constexpr int W = 256;
constexpr int D = 32;
}

__global__ __launch_bounds__(128, 8)
void cost_volume_kernel(const float* __restrict__ left,
                        const float* __restrict__ right,
                        float* __restrict__ out) {
    // slbuf: floats [0..255] = left row, [256..291] = zero tail (36 floats).
    // srbuf: floats [0..31] = zero head, [32..287] = right row.
    //   srbuf float j holds right-row element (j - 32).
    __shared__ float4 slbuf[73];  // 292 floats
    __shared__ float4 srbuf[72];  // 288 floats

    const int blk = blockIdx.x;          // b*C*H + c*H + h
    const int h = blk & (H - 1);
    const int c = (blk >> 7) & (C - 1);
    const int b = blk >> 12;

    const int tid  = threadIdx.x;        // 0..127
    const int half = tid >> 6;           // 0 = left, 1 = right
    const int l64  = tid & 63;           // float4 column along W
    const int w4   = l64 << 2;           // 0,4,...,252

    const size_t in_off = ((((size_t)b * C + c) * H) + h) * W;

    // ---- stage rows + zero pads ----
    if (tid < 64) {
        slbuf[tid] = reinterpret_cast<const float4*>(left + in_off)[tid];
    } else {
        srbuf[8 + (tid - 64)] =
            reinterpret_cast<const float4*>(right + in_off)[tid - 64];
    }
    if (tid < 9)  slbuf[64 + tid] = make_float4(0.f, 0.f, 0.f, 0.f);
    else if (tid < 17) srbuf[tid - 9] = make_float4(0.f, 0.f, 0.f, 0.f);
    __syncthreads();

    // ---- load 36-float window into registers (9 x LDS.128) ----
    // Left  thread: f[k] = left_row[w4 + k]           (k = 0..35)
    // Right thread: f[k] = right_row[w4 - 32 + k]     (k = 0..35)
    // Both map to buffer float4 indices [l64 .. l64+8].
    float f[36];
    {
        const float4* buf = half ? srbuf : slbuf;
        #pragma unroll
        for (int i = 0; i < 9; i++) {
            float4 q = buf[l64 + i];
            f[4 * i + 0] = q.x;
            f[4 * i + 1] = q.y;
            f[4 * i + 2] = q.z;
            f[4 * i + 3] = q.w;
        }
    }

    // ---- emit 32 disparity planes ----
    const size_t dstride = (size_t)H * W;  // 32768 floats per d-plane
    float* dst = out
        + ((size_t)(b * 2 * C + half * C + c) * D) * dstride
        + (size_t)h * W + w4;

    if (half == 0) {
        // out[d] = left_row[w4 + d .. w4 + d + 3] = f[d .. d+3]
        #pragma unroll
        for (int d = 0; d < D; d++) {
            float4 v = make_float4(f[d], f[d + 1], f[d + 2], f[d + 3]);
            *reinterpret_cast<float4*>(dst + (size_t)d * dstride) = v;
        }
    } else {
        // out[d] = right_row[w4 - d .. w4 - d + 3] = f[32-d .. 35-d]
        #pragma unroll
        for (int d = 0; d < D; d++) {
            float4 v = make_float4(f[32 - d], f[33 - d], f[34 - d], f[35 - d]);
            *reinterpret_cast<float4*>(dst + (size_t)d * dstride) = v;
        }
    }
}

extern "C" void kernel_launch(void* const* d_in, const int* in_sizes, int n_in,
                              void* d_out, int out_size) {
    const float* left  = (const float*)d_in[0];
    const float* right = (const float*)d_in[1];
    float* out = (float*)d_out;

    (void)in_sizes; (void)n_in; (void)out_size;

    const int grid = B * C * H;  // 8192 CTAs
    cost_volume_kernel<<<grid, 128>>>(left, right, out);
}

// round 3
// speedup vs baseline: 1.6089x; 1.0183x over previous
#include <cuda_runtime.h>

// CostVolume: left,right [B,C,H,W] f32 -> out [B,2C,D,H,W] f32
//   out[b, c,      d, h, w] = (w+d < W) ? left [b,c,h,w+d] : 0
//   out[b, C + c,  d, h, w] = (w-d >= 0)? right[b,c,h,w-d] : 0
//
// Fixed shapes: B=2, C=32, H=128, W=256, D=32.
//
// R3: one CTA (256 thr) per (b,c,h) row. Thread -> (half, dhalf, column):
//   half  = tid>>7        (0 = left, 1 = right)
//   dhalf = (tid>>6)&1    (d in [16*dhalf, 16*dhalf+16))
//   l64   = tid&63        (float4 column, w4 = 4*l64)
// Each thread loads a 20-float register window (5 x LDS.128) from a
// zero-padded smem row, then emits 16 x STG.128 by static register
// selection. Lower regs (~38 vs 62) -> ~2x resident warps vs R2.

namespace {
constexpr int B = 2;
constexpr int C = 32;
constexpr int H = 128;
constexpr int W = 256;
constexpr int D = 32;
}

__global__ __launch_bounds__(256)
void cost_volume_kernel(const float* __restrict__ left,
                        const float* __restrict__ right,
                        float* __restrict__ out) {
    // slbuf floats: [0..255] = left row, [256..287] = zero tail.
    // srbuf floats: [0..31] = zero head, [32..287] = right row
    //               (srbuf float j holds right_row[j-32]).
    __shared__ float4 slbuf[72];
    __shared__ float4 srbuf[72];

    const int blk = blockIdx.x;          // b*C*H + c*H + h
    const int h = blk & (H - 1);
    const int c = (blk >> 7) & (C - 1);
    const int b = blk >> 12;

    const int tid   = threadIdx.x;       // 0..255
    const int half  = tid >> 7;          // 0 = left, 1 = right
    const int dhalf = (tid >> 6) & 1;    // d block
    const int l64   = tid & 63;          // float4 column
    const int w4    = l64 << 2;
    const int d0    = dhalf << 4;        // 0 or 16

    const size_t in_off = ((((size_t)b * C + c) * H) + h) * W;

    // ---- stage rows + zero pads ----
    if (tid < 64) {
        slbuf[tid] = reinterpret_cast<const float4*>(left + in_off)[tid];
    } else if (tid < 128) {
        srbuf[8 + (tid - 64)] =
            reinterpret_cast<const float4*>(right + in_off)[tid - 64];
    } else if (tid < 136) {
        slbuf[64 + (tid - 128)] = make_float4(0.f, 0.f, 0.f, 0.f);
    } else if (tid < 144) {
        srbuf[tid - 136] = make_float4(0.f, 0.f, 0.f, 0.f);
    }
    __syncthreads();

    // ---- 20-float register window (5 x LDS.128) ----
    // Left  thread: f[k] = left_row [w4 + d0 + k],      k = 0..19
    //   -> slbuf float4 index base = l64 + 4*dhalf
    // Right thread: f[k] = right_row[w4 - d0 - 16 + k], k = 0..19
    //   -> srbuf float4 index base = (4*l64 - 16*dhalf + 16 + 32)/4
    //                              = l64 + 4 - 4*dhalf   (+8 head pad included)
    float f[20];
    {
        const float4* buf  = half ? srbuf : slbuf;
        const int     base = half ? (l64 + 4 - 4 * dhalf) : (l64 + 4 * dhalf);
        #pragma unroll
        for (int i = 0; i < 5; i++) {
            float4 q = buf[base + i];
            f[4 * i + 0] = q.x;
            f[4 * i + 1] = q.y;
            f[4 * i + 2] = q.z;
            f[4 * i + 3] = q.w;
        }
    }

    // ---- emit 16 disparity planes ----
    const size_t dstride = (size_t)H * W;  // 32768 floats per d-plane
    float* dst = out
        + ((size_t)(b * 2 * C + half * C + c) * D + d0) * dstride
        + (size_t)h * W + w4;

    if (half == 0) {
        // d = d0 + dd: out = left_row[w4+d .. w4+d+3] = f[dd .. dd+3]
        #pragma unroll
        for (int dd = 0; dd < 16; dd++) {
            float4 v = make_float4(f[dd], f[dd + 1], f[dd + 2], f[dd + 3]);
            *reinterpret_cast<float4*>(dst + (size_t)dd * dstride) = v;
        }
    } else {
        // d = d0 + dd: out = right_row[w4-d .. w4-d+3] = f[16-dd .. 19-dd]
        #pragma unroll
        for (int dd = 0; dd < 16; dd++) {
            float4 v = make_float4(f[16 - dd], f[17 - dd], f[18 - dd], f[19 - dd]);
            *reinterpret_cast<float4*>(dst + (size_t)dd * dstride) = v;
        }
    }
}

extern "C" void kernel_launch(void* const* d_in, const int* in_sizes, int n_in,
                              void* d_out, int out_size) {
    const float* left  = (const float*)d_in[0];
    const float* right = (const float*)d_in[1];
    float* out = (float*)d_out;

    (void)in_sizes; (void)n_in; (void)out_size;

    const int grid = B * C * H;  // 8192 CTAs
    cost_volume_kernel<<<grid, 256>>>(left, right, out);
}

// round 4
// speedup vs baseline: 1.7365x; 1.0793x over previous
#include <cuda_runtime.h>

// CostVolume: left,right [B,C,H,W] f32 -> out [B,2C,D,H,W] f32
//   out[b, c,      d, h, w] = (w+d < W) ? left [b,c,h,w+d] : 0
//   out[b, C + c,  d, h, w] = (w-d >= 0)? right[b,c,h,w-d] : 0
//
// Fixed shapes: B=2, C=32, H=128, W=256, D=32.
//
// R4: identical structure to R3 (one 256-thread CTA per (b,c,h) row;
// 20-float register window from zero-padded smem; 16 x STG.128 per thread)
// but all output stores use st.global.cs (streaming / evict-first) since the
// 536 MB output is write-once and should not linger in L2. The kernel is at
// the LTS/HBM-write ceiling (~6.0-6.3 TB/s measured across occ 45% and 69%),
// so store policy is the remaining lever.

namespace {
constexpr int B = 2;
constexpr int C = 32;
constexpr int H = 128;
constexpr int W = 256;
constexpr int D = 32;
}

__device__ __forceinline__ void stcs128(float* p, float4 v) {
    __stcs(reinterpret_cast<float4*>(p), v);
}

__global__ __launch_bounds__(256)
void cost_volume_kernel(const float* __restrict__ left,
                        const float* __restrict__ right,
                        float* __restrict__ out) {
    // slbuf floats: [0..255] = left row, [256..287] = zero tail.
    // srbuf floats: [0..31] = zero head, [32..287] = right row
    //               (srbuf float j holds right_row[j-32]).
    __shared__ float4 slbuf[72];
    __shared__ float4 srbuf[72];

    const int blk = blockIdx.x;          // b*C*H + c*H + h
    const int h = blk & (H - 1);
    const int c = (blk >> 7) & (C - 1);
    const int b = blk >> 12;

    const int tid   = threadIdx.x;       // 0..255
    const int half  = tid >> 7;          // 0 = left, 1 = right
    const int dhalf = (tid >> 6) & 1;    // d block
    const int l64   = tid & 63;          // float4 column
    const int w4    = l64 << 2;
    const int d0    = dhalf << 4;        // 0 or 16

    const size_t in_off = ((((size_t)b * C + c) * H) + h) * W;

    // ---- stage rows + zero pads ----
    if (tid < 64) {
        slbuf[tid] = reinterpret_cast<const float4*>(left + in_off)[tid];
    } else if (tid < 128) {
        srbuf[8 + (tid - 64)] =
            reinterpret_cast<const float4*>(right + in_off)[tid - 64];
    } else if (tid < 136) {
        slbuf[64 + (tid - 128)] = make_float4(0.f, 0.f, 0.f, 0.f);
    } else if (tid < 144) {
        srbuf[tid - 136] = make_float4(0.f, 0.f, 0.f, 0.f);
    }
    __syncthreads();

    // ---- 20-float register window (5 x LDS.128) ----
    // Left  thread: f[k] = left_row [w4 + d0 + k],      k = 0..19
    // Right thread: f[k] = right_row[w4 - d0 - 16 + k], k = 0..19
    float f[20];
    {
        const float4* buf  = half ? srbuf : slbuf;
        const int     base = half ? (l64 + 4 - 4 * dhalf) : (l64 + 4 * dhalf);
        #pragma unroll
        for (int i = 0; i < 5; i++) {
            float4 q = buf[base + i];
            f[4 * i + 0] = q.x;
            f[4 * i + 1] = q.y;
            f[4 * i + 2] = q.z;
            f[4 * i + 3] = q.w;
        }
    }

    // ---- emit 16 disparity planes (streaming stores) ----
    const size_t dstride = (size_t)H * W;  // 32768 floats per d-plane
    float* dst = out
        + ((size_t)(b * 2 * C + half * C + c) * D + d0) * dstride
        + (size_t)h * W + w4;

    if (half == 0) {
        // d = d0 + dd: out = left_row[w4+d .. w4+d+3] = f[dd .. dd+3]
        #pragma unroll
        for (int dd = 0; dd < 16; dd++) {
            float4 v = make_float4(f[dd], f[dd + 1], f[dd + 2], f[dd + 3]);
            stcs128(dst + (size_t)dd * dstride, v);
        }
    } else {
        // d = d0 + dd: out = right_row[w4-d .. w4-d+3] = f[16-dd .. 19-dd]
        #pragma unroll
        for (int dd = 0; dd < 16; dd++) {
            float4 v = make_float4(f[16 - dd], f[17 - dd], f[18 - dd], f[19 - dd]);
            stcs128(dst + (size_t)dd * dstride, v);
        }
    }
}

extern "C" void kernel_launch(void* const* d_in, const int* in_sizes, int n_in,
                              void* d_out, int out_size) {
    const float* left  = (const float*)d_in[0];
    const float* right = (const float*)d_in[1];
    float* out = (float*)d_out;

    (void)in_sizes; (void)n_in; (void)out_size;

    const int grid = B * C * H;  // 8192 CTAs
    cost_volume_kernel<<<grid, 256>>>(left, right, out);
}